// round 1
// baseline (speedup 1.0000x reference)
#include <cuda_runtime.h>
#include <cuda_bf16.h>

#define Bb 4
#define Hh 200
#define Ww 200
#define Tt 5
#define Cc 64
#define C4 16               // float4 per channel dim: 64/4
#define PIX_F4 (Tt * C4)    // 80 float4 per (b,h,w) pixel
#define TOTAL (Bb * Hh * Ww * Tt * C4)   // 12,800,000 float4 elements

__global__ __launch_bounds__(256) void align_bev_kernel(
    const float4* __restrict__ in,
    const float*  __restrict__ ego,
    float4* __restrict__ out)
{
    int i = blockIdx.x * blockDim.x + threadIdx.x;
    if (i >= TOTAL) return;

    int c4   = i & 15;          // 0..15
    int rest = i >> 4;          // pix*5 + t
    int t    = rest % Tt;
    int pix  = rest / Tt;

    // last time-slice: passthrough copy
    if (t == Tt - 1) {
        out[i] = in[i];
        return;
    }

    int w  = pix % Ww;
    int hb = pix / Ww;
    int h  = hb % Hh;
    int b  = hb / Hh;

    // per-batch ego transform (12-float tensor, L1 broadcast)
    float dx   = ego[3 * b + 0];
    float dy   = ego[3 * b + 1];
    float dyaw = ego[3 * b + 2];
    float dxn = dx / 100.0f;    // MAP_RANGE/2 = 100
    float dyn = dy / 100.0f;

    float s, c;
    sincosf(dyaw, &s, &c);
    float tx = -(c * dxn + s * dyn);
    float ty =  s * dxn - c * dyn;

    float xsv = (2.0f * (float)w + 1.0f) / (float)Ww - 1.0f;
    float ysv = (2.0f * (float)h + 1.0f) / (float)Hh - 1.0f;

    float gx =  c * xsv + s * ysv + tx;
    float gy = -s * xsv + c * ysv + ty;

    float ixv = ((gx + 1.0f) * (float)Ww - 1.0f) * 0.5f;
    float iyv = ((gy + 1.0f) * (float)Hh - 1.0f) * 0.5f;

    float ix0f = floorf(ixv);
    float iy0f = floorf(iyv);
    float wx1 = ixv - ix0f, wx0 = 1.0f - wx1;
    float wy1 = iyv - iy0f, wy0 = 1.0f - wy1;
    float ix1f = ix0f + 1.0f;
    float iy1f = iy0f + 1.0f;

    // validity masks (before clamping)
    float mx0 = (ix0f >= 0.0f && ix0f <= (float)(Ww - 1)) ? 1.0f : 0.0f;
    float mx1 = (ix1f >= 0.0f && ix1f <= (float)(Ww - 1)) ? 1.0f : 0.0f;
    float my0 = (iy0f >= 0.0f && iy0f <= (float)(Hh - 1)) ? 1.0f : 0.0f;
    float my1 = (iy1f >= 0.0f && iy1f <= (float)(Hh - 1)) ? 1.0f : 0.0f;

    // clamped integer indices
    int x0 = (int)fminf(fmaxf(ix0f, 0.0f), (float)(Ww - 1));
    int x1 = (int)fminf(fmaxf(ix1f, 0.0f), (float)(Ww - 1));
    int y0 = (int)fminf(fmaxf(iy0f, 0.0f), (float)(Hh - 1));
    int y1 = (int)fminf(fmaxf(iy1f, 0.0f), (float)(Hh - 1));

    float w00 = wy0 * wx0 * (my0 * mx0);
    float w01 = wy0 * wx1 * (my0 * mx1);
    float w10 = wy1 * wx0 * (my1 * mx0);
    float w11 = wy1 * wx1 * (my1 * mx1);

    long  baseB = (long)b * (Hh * Ww);
    int   tc = t * C4 + c4;

    const float4* p00 = in + ((baseB + (long)y0 * Ww + x0) * PIX_F4 + tc);
    const float4* p01 = in + ((baseB + (long)y0 * Ww + x1) * PIX_F4 + tc);
    const float4* p10 = in + ((baseB + (long)y1 * Ww + x0) * PIX_F4 + tc);
    const float4* p11 = in + ((baseB + (long)y1 * Ww + x1) * PIX_F4 + tc);

    float4 v00 = *p00;
    float4 v01 = *p01;
    float4 v10 = *p10;
    float4 v11 = *p11;

    float4 r;
    r.x = w00 * v00.x + w01 * v01.x + w10 * v10.x + w11 * v11.x;
    r.y = w00 * v00.y + w01 * v01.y + w10 * v10.y + w11 * v11.y;
    r.z = w00 * v00.z + w01 * v01.z + w10 * v10.z + w11 * v11.z;
    r.w = w00 * v00.w + w01 * v01.w + w10 * v10.w + w11 * v11.w;

    out[i] = r;
}

extern "C" void kernel_launch(void* const* d_in, const int* in_sizes, int n_in,
                              void* d_out, int out_size)
{
    const float4* in  = (const float4*)d_in[0];   // raw_bev_cache (4,200,200,5,64) f32
    const float*  ego = (const float*)d_in[1];    // delta_ego_motion (4,3) f32
    float4* out = (float4*)d_out;

    int threads = 256;
    int blocks  = (TOTAL + threads - 1) / threads;
    align_bev_kernel<<<blocks, threads>>>(in, ego, out);
}

// round 2
// speedup vs baseline: 1.3016x; 1.3016x over previous
#include <cuda_runtime.h>
#include <cuda_bf16.h>

#define Bb 4
#define Hh 200
#define Ww 200
#define Tt 5
#define C4 16                 // float4 per 64-channel dim
#define PIX_F4 (Tt * C4)      // 80 float4 per (b,h,w) pixel
#define NPIX (Bb * Hh * Ww)   // 160,000 pixels
#define NTHREADS2 (NPIX * C4) // 2,560,000 pass-2 threads

struct __align__(32) PixInfo {
    float w00, w01, w10, w11;
    int   o00, o01, o10, o11;   // corner pixel base offsets in float4 units (pix*80)
};

__device__ PixInfo g_pixinfo[NPIX];

// ---------------- Pass 1: per-pixel transform (runs once per pixel) ----------------
__global__ __launch_bounds__(256) void precompute_kernel(const float* __restrict__ ego)
{
    int pix = blockIdx.x * blockDim.x + threadIdx.x;
    if (pix >= NPIX) return;

    int w  = pix % Ww;
    int hb = pix / Ww;
    int h  = hb % Hh;
    int b  = hb / Hh;

    float dxn = ego[3 * b + 0] / 100.0f;   // MAP_RANGE/2 = 100
    float dyn = ego[3 * b + 1] / 100.0f;
    float dyaw = ego[3 * b + 2];

    float s, c;
    sincosf(dyaw, &s, &c);
    float tx = -(c * dxn + s * dyn);
    float ty =  s * dxn - c * dyn;

    float xsv = (2.0f * (float)w + 1.0f) / (float)Ww - 1.0f;
    float ysv = (2.0f * (float)h + 1.0f) / (float)Hh - 1.0f;

    float gx =  c * xsv + s * ysv + tx;
    float gy = -s * xsv + c * ysv + ty;

    float ixv = ((gx + 1.0f) * (float)Ww - 1.0f) * 0.5f;
    float iyv = ((gy + 1.0f) * (float)Hh - 1.0f) * 0.5f;

    float ix0f = floorf(ixv);
    float iy0f = floorf(iyv);
    float wx1 = ixv - ix0f, wx0 = 1.0f - wx1;
    float wy1 = iyv - iy0f, wy0 = 1.0f - wy1;
    float ix1f = ix0f + 1.0f;
    float iy1f = iy0f + 1.0f;

    float mx0 = (ix0f >= 0.0f && ix0f <= (float)(Ww - 1)) ? 1.0f : 0.0f;
    float mx1 = (ix1f >= 0.0f && ix1f <= (float)(Ww - 1)) ? 1.0f : 0.0f;
    float my0 = (iy0f >= 0.0f && iy0f <= (float)(Hh - 1)) ? 1.0f : 0.0f;
    float my1 = (iy1f >= 0.0f && iy1f <= (float)(Hh - 1)) ? 1.0f : 0.0f;

    int x0 = (int)fminf(fmaxf(ix0f, 0.0f), (float)(Ww - 1));
    int x1 = (int)fminf(fmaxf(ix1f, 0.0f), (float)(Ww - 1));
    int y0 = (int)fminf(fmaxf(iy0f, 0.0f), (float)(Hh - 1));
    int y1 = (int)fminf(fmaxf(iy1f, 0.0f), (float)(Hh - 1));

    int baseB = b * (Hh * Ww);

    PixInfo pi;
    pi.w00 = wy0 * wx0 * (my0 * mx0);
    pi.w01 = wy0 * wx1 * (my0 * mx1);
    pi.w10 = wy1 * wx0 * (my1 * mx0);
    pi.w11 = wy1 * wx1 * (my1 * mx1);
    pi.o00 = (baseB + y0 * Ww + x0) * PIX_F4;
    pi.o01 = (baseB + y0 * Ww + x1) * PIX_F4;
    pi.o10 = (baseB + y1 * Ww + x0) * PIX_F4;
    pi.o11 = (baseB + y1 * Ww + x1) * PIX_F4;

    g_pixinfo[pix] = pi;
}

// ---------------- Pass 2: gather + blend (memory-bound hot loop) ----------------
__global__ __launch_bounds__(256) void gather_kernel(
    const float4* __restrict__ in,
    float4* __restrict__ out)
{
    int j = blockIdx.x * blockDim.x + threadIdx.x;
    if (j >= NTHREADS2) return;

    int c4  = j & 15;
    int pix = j >> 4;

    PixInfo pi = g_pixinfo[pix];   // 32B, broadcast across the 16 threads sharing pix

    int outbase = pix * PIX_F4;

    #pragma unroll
    for (int t = 0; t < Tt - 1; t++) {
        int tc = t * C4 + c4;
        float4 v00 = in[pi.o00 + tc];
        float4 v01 = in[pi.o01 + tc];
        float4 v10 = in[pi.o10 + tc];
        float4 v11 = in[pi.o11 + tc];

        float4 r;
        r.x = pi.w00 * v00.x + pi.w01 * v01.x + pi.w10 * v10.x + pi.w11 * v11.x;
        r.y = pi.w00 * v00.y + pi.w01 * v01.y + pi.w10 * v10.y + pi.w11 * v11.y;
        r.z = pi.w00 * v00.z + pi.w01 * v01.z + pi.w10 * v10.z + pi.w11 * v11.z;
        r.w = pi.w00 * v00.w + pi.w01 * v01.w + pi.w10 * v10.w + pi.w11 * v11.w;

        out[outbase + tc] = r;
    }

    // t = 4 passthrough
    int tc4 = (Tt - 1) * C4 + c4;
    out[outbase + tc4] = in[outbase + tc4];
}

extern "C" void kernel_launch(void* const* d_in, const int* in_sizes, int n_in,
                              void* d_out, int out_size)
{
    const float4* in  = (const float4*)d_in[0];   // raw_bev_cache (4,200,200,5,64) f32
    const float*  ego = (const float*)d_in[1];    // delta_ego_motion (4,3) f32
    float4* out = (float4*)d_out;

    precompute_kernel<<<(NPIX + 255) / 256, 256>>>(ego);
    gather_kernel<<<(NTHREADS2 + 255) / 256, 256>>>(in, out);
}

// round 3
// speedup vs baseline: 1.3252x; 1.0181x over previous
#include <cuda_runtime.h>
#include <cuda_bf16.h>

#define Bb 4
#define Hh 200
#define Ww 200
#define Tt 5
#define C4 16                 // float4 per 64-channel dim
#define PIX_F4 (Tt * C4)      // 80 float4 per (b,h,w) pixel
#define NPIX (Bb * Hh * Ww)   // 160,000 pixels
#define NTHREADS (NPIX * C4)  // 2,560,000 threads

__global__ __launch_bounds__(256) void align_bev_fused(
    const float4* __restrict__ in,
    const float*  __restrict__ ego,
    float4* __restrict__ out)
{
    int j = blockIdx.x * blockDim.x + threadIdx.x;
    if (j >= NTHREADS) return;

    int c4  = j & 15;
    int pix = j >> 4;

    int w  = pix % Ww;
    int hb = pix / Ww;
    int h  = hb % Hh;
    int b  = hb / Hh;

    // ---- per-pixel transform (amortized over 5 t-slices per thread) ----
    float dxn  = ego[3 * b + 0] * 0.01f;    // / (MAP_RANGE/2 = 100)
    float dyn  = ego[3 * b + 1] * 0.01f;
    float dyaw = ego[3 * b + 2];

    float s, c;
    sincosf(dyaw, &s, &c);
    float tx = -(c * dxn + s * dyn);
    float ty =  s * dxn - c * dyn;

    const float invW = 1.0f / (float)Ww;
    const float invH = 1.0f / (float)Hh;
    float xsv = (2.0f * (float)w + 1.0f) * invW - 1.0f;
    float ysv = (2.0f * (float)h + 1.0f) * invH - 1.0f;

    float gx =  c * xsv + s * ysv + tx;
    float gy = -s * xsv + c * ysv + ty;

    float ixv = ((gx + 1.0f) * (float)Ww - 1.0f) * 0.5f;
    float iyv = ((gy + 1.0f) * (float)Hh - 1.0f) * 0.5f;

    float ix0f = floorf(ixv);
    float iy0f = floorf(iyv);
    float wx1 = ixv - ix0f, wx0 = 1.0f - wx1;
    float wy1 = iyv - iy0f, wy0 = 1.0f - wy1;
    float ix1f = ix0f + 1.0f;
    float iy1f = iy0f + 1.0f;

    float mx0 = (ix0f >= 0.0f && ix0f <= (float)(Ww - 1)) ? 1.0f : 0.0f;
    float mx1 = (ix1f >= 0.0f && ix1f <= (float)(Ww - 1)) ? 1.0f : 0.0f;
    float my0 = (iy0f >= 0.0f && iy0f <= (float)(Hh - 1)) ? 1.0f : 0.0f;
    float my1 = (iy1f >= 0.0f && iy1f <= (float)(Hh - 1)) ? 1.0f : 0.0f;

    int x0 = (int)fminf(fmaxf(ix0f, 0.0f), (float)(Ww - 1));
    int x1 = (int)fminf(fmaxf(ix1f, 0.0f), (float)(Ww - 1));
    int y0 = (int)fminf(fmaxf(iy0f, 0.0f), (float)(Hh - 1));
    int y1 = (int)fminf(fmaxf(iy1f, 0.0f), (float)(Hh - 1));

    float w00 = wy0 * wx0 * (my0 * mx0);
    float w01 = wy0 * wx1 * (my0 * mx1);
    float w10 = wy1 * wx0 * (my1 * mx0);
    float w11 = wy1 * wx1 * (my1 * mx1);

    int baseB = b * (Hh * Ww);
    int o00 = (baseB + y0 * Ww + x0) * PIX_F4 + c4;
    int o01 = (baseB + y0 * Ww + x1) * PIX_F4 + c4;
    int o10 = (baseB + y1 * Ww + x0) * PIX_F4 + c4;
    int o11 = (baseB + y1 * Ww + x1) * PIX_F4 + c4;

    int outbase = pix * PIX_F4 + c4;

    // ---- gather + blend: 16 corner loads (reused lines, default caching),
    //      streaming stores (output is never re-read) ----
    #pragma unroll
    for (int t = 0; t < Tt - 1; t++) {
        int tc = t * C4;
        float4 v00 = __ldg(&in[o00 + tc]);
        float4 v01 = __ldg(&in[o01 + tc]);
        float4 v10 = __ldg(&in[o10 + tc]);
        float4 v11 = __ldg(&in[o11 + tc]);

        float4 r;
        r.x = w00 * v00.x + w01 * v01.x + w10 * v10.x + w11 * v11.x;
        r.y = w00 * v00.y + w01 * v01.y + w10 * v10.y + w11 * v11.y;
        r.z = w00 * v00.z + w01 * v01.z + w10 * v10.z + w11 * v11.z;
        r.w = w00 * v00.w + w01 * v01.w + w10 * v10.w + w11 * v11.w;

        __stcs(&out[outbase + tc], r);
    }

    // t = 4 passthrough: zero reuse on both sides -> stream both
    int tc4 = (Tt - 1) * C4;
    float4 cur = __ldcs(&in[outbase + tc4]);
    __stcs(&out[outbase + tc4], cur);
}

extern "C" void kernel_launch(void* const* d_in, const int* in_sizes, int n_in,
                              void* d_out, int out_size)
{
    const float4* in  = (const float4*)d_in[0];   // raw_bev_cache (4,200,200,5,64) f32
    const float*  ego = (const float*)d_in[1];    // delta_ego_motion (4,3) f32
    float4* out = (float4*)d_out;

    align_bev_fused<<<(NTHREADS + 255) / 256, 256>>>(in, ego, out);
}

// round 4
// speedup vs baseline: 1.3325x; 1.0055x over previous
#include <cuda_runtime.h>
#include <cuda_bf16.h>

#define Bb 4
#define Hh 200
#define Ww 200
#define Tt 5
#define C4 16                 // float4 per 64-channel dim
#define PIX_F4 (Tt * C4)      // 80 float4 per (b,h,w) pixel

// Tiling: block = 8(w) x 2(h) pixels x 16 c4 = 256 threads.
// Supertile = 5 tiles_x x 10 tiles_y = 40(w) x 20(h) pixels = 50 blocks.
// Per batch: 5 stx x 5... (200/40=5) x (200/20=10) = 50 supertiles -> 2500 blocks.
#define BLOCKS_PER_BATCH 2500
#define BLOCKS_PER_ST 50
#define TOTAL_BLOCKS (Bb * BLOCKS_PER_BATCH)   // 10000

__global__ __launch_bounds__(256) void align_bev_tiled(
    const float4* __restrict__ in,
    const float*  __restrict__ ego,
    float4* __restrict__ out)
{
    // ---- 2D-local block decode ----
    int bid   = blockIdx.x;
    int b     = bid / BLOCKS_PER_BATCH;
    int r     = bid - b * BLOCKS_PER_BATCH;
    int st    = r / BLOCKS_PER_ST;          // 0..49 supertile within batch
    int inner = r - st * BLOCKS_PER_ST;     // 0..49 tile within supertile
    int stx   = st % 5;                     // 5 supertiles across w
    int sty   = st / 5;                     // 10 supertiles across h
    int tx    = inner % 5;                  // 5 tiles across supertile w
    int ty    = inner / 5;                  // 10 tiles across supertile h
    int tile_x = stx * 5 + tx;              // 0..24
    int tile_y = sty * 10 + ty;             // 0..99

    int c4 = threadIdx.x & 15;
    int px = threadIdx.x >> 4;              // 0..15 pixel within tile
    int w  = tile_x * 8 + (px & 7);
    int h  = tile_y * 2 + (px >> 3);

    int pix = (b * Hh + h) * Ww + w;

    // ---- per-pixel transform ----
    float dxn  = ego[3 * b + 0] * 0.01f;    // / (MAP_RANGE/2 = 100)
    float dyn  = ego[3 * b + 1] * 0.01f;
    float dyaw = ego[3 * b + 2];

    float s, c;
    sincosf(dyaw, &s, &c);
    float tfx = -(c * dxn + s * dyn);
    float tfy =  s * dxn - c * dyn;

    const float invW = 1.0f / (float)Ww;
    const float invH = 1.0f / (float)Hh;
    float xsv = (2.0f * (float)w + 1.0f) * invW - 1.0f;
    float ysv = (2.0f * (float)h + 1.0f) * invH - 1.0f;

    float gx =  c * xsv + s * ysv + tfx;
    float gy = -s * xsv + c * ysv + tfy;

    float ixv = ((gx + 1.0f) * (float)Ww - 1.0f) * 0.5f;
    float iyv = ((gy + 1.0f) * (float)Hh - 1.0f) * 0.5f;

    float ix0f = floorf(ixv);
    float iy0f = floorf(iyv);
    float wx1 = ixv - ix0f, wx0 = 1.0f - wx1;
    float wy1 = iyv - iy0f, wy0 = 1.0f - wy1;
    float ix1f = ix0f + 1.0f;
    float iy1f = iy0f + 1.0f;

    float mx0 = (ix0f >= 0.0f && ix0f <= (float)(Ww - 1)) ? 1.0f : 0.0f;
    float mx1 = (ix1f >= 0.0f && ix1f <= (float)(Ww - 1)) ? 1.0f : 0.0f;
    float my0 = (iy0f >= 0.0f && iy0f <= (float)(Hh - 1)) ? 1.0f : 0.0f;
    float my1 = (iy1f >= 0.0f && iy1f <= (float)(Hh - 1)) ? 1.0f : 0.0f;

    int x0 = (int)fminf(fmaxf(ix0f, 0.0f), (float)(Ww - 1));
    int x1 = (int)fminf(fmaxf(ix1f, 0.0f), (float)(Ww - 1));
    int y0 = (int)fminf(fmaxf(iy0f, 0.0f), (float)(Hh - 1));
    int y1 = (int)fminf(fmaxf(iy1f, 0.0f), (float)(Hh - 1));

    float w00 = wy0 * wx0 * (my0 * mx0);
    float w01 = wy0 * wx1 * (my0 * mx1);
    float w10 = wy1 * wx0 * (my1 * mx0);
    float w11 = wy1 * wx1 * (my1 * mx1);

    int baseB = b * (Hh * Ww);
    int o00 = (baseB + y0 * Ww + x0) * PIX_F4 + c4;
    int o01 = (baseB + y0 * Ww + x1) * PIX_F4 + c4;
    int o10 = (baseB + y1 * Ww + x0) * PIX_F4 + c4;
    int o11 = (baseB + y1 * Ww + x1) * PIX_F4 + c4;

    int outbase = pix * PIX_F4 + c4;

    // ---- front-load ALL 16 corner float4s (max MLP), then blend ----
    float4 v00[4], v01[4], v10[4], v11[4];
    #pragma unroll
    for (int t = 0; t < Tt - 1; t++) {
        int tc = t * C4;
        v00[t] = __ldg(&in[o00 + tc]);
        v01[t] = __ldg(&in[o01 + tc]);
        v10[t] = __ldg(&in[o10 + tc]);
        v11[t] = __ldg(&in[o11 + tc]);
    }

    #pragma unroll
    for (int t = 0; t < Tt - 1; t++) {
        float4 r4;
        r4.x = w00 * v00[t].x + w01 * v01[t].x + w10 * v10[t].x + w11 * v11[t].x;
        r4.y = w00 * v00[t].y + w01 * v01[t].y + w10 * v10[t].y + w11 * v11[t].y;
        r4.z = w00 * v00[t].z + w01 * v01[t].z + w10 * v10[t].z + w11 * v11[t].z;
        r4.w = w00 * v00[t].w + w01 * v01[t].w + w10 * v10[t].w + w11 * v11[t].w;
        __stcs(&out[outbase + t * C4], r4);
    }

    // t = 4 passthrough: zero reuse either side -> stream both ways
    int tc4 = (Tt - 1) * C4;
    float4 cur = __ldcs(&in[outbase + tc4]);
    __stcs(&out[outbase + tc4], cur);
}

extern "C" void kernel_launch(void* const* d_in, const int* in_sizes, int n_in,
                              void* d_out, int out_size)
{
    const float4* in  = (const float4*)d_in[0];   // raw_bev_cache (4,200,200,5,64) f32
    const float*  ego = (const float*)d_in[1];    // delta_ego_motion (4,3) f32
    float4* out = (float4*)d_out;

    align_bev_tiled<<<TOTAL_BLOCKS, 256>>>(in, ego, out);
}

// round 5
// speedup vs baseline: 1.5089x; 1.1324x over previous
#include <cuda_runtime.h>
#include <cuda_bf16.h>

#define Bb 4
#define Hh 200
#define Ww 200
#define Tt 5
#define C4 16                 // float4 per 64-channel dim
#define PIX_F4 (Tt * C4)      // 80 float4 per (b,h,w) pixel

// Tiling: block = 8(w) x 2(h) pixels x 16 c4 = 256 threads.
#define BLOCKS_PER_BATCH 2500
#define BLOCKS_PER_ST 50
#define TOTAL_BLOCKS (Bb * BLOCKS_PER_BATCH)   // 10000

__global__ __launch_bounds__(256, 4) void align_bev_mlp(
    const float4* __restrict__ in,
    const float*  __restrict__ ego,
    float4* __restrict__ out)
{
    // ---- 2D-local block decode ----
    int bid   = blockIdx.x;
    int b     = bid / BLOCKS_PER_BATCH;
    int r     = bid - b * BLOCKS_PER_BATCH;
    int st    = r / BLOCKS_PER_ST;
    int inner = r - st * BLOCKS_PER_ST;
    int stx   = st % 5;
    int sty   = st / 5;
    int tx    = inner % 5;
    int ty    = inner / 5;
    int tile_x = stx * 5 + tx;              // 0..24
    int tile_y = sty * 10 + ty;             // 0..99

    int c4 = threadIdx.x & 15;
    int px = threadIdx.x >> 4;              // 0..15 pixel within tile
    int w  = tile_x * 8 + (px & 7);
    int h  = tile_y * 2 + (px >> 3);

    int pix = (b * Hh + h) * Ww + w;

    // ---- per-pixel transform ----
    float dxn  = ego[3 * b + 0] * 0.01f;    // / (MAP_RANGE/2 = 100)
    float dyn  = ego[3 * b + 1] * 0.01f;
    float dyaw = ego[3 * b + 2];

    float s, c;
    sincosf(dyaw, &s, &c);
    float tfx = -(c * dxn + s * dyn);
    float tfy =  s * dxn - c * dyn;

    const float invW = 1.0f / (float)Ww;
    const float invH = 1.0f / (float)Hh;
    float xsv = (2.0f * (float)w + 1.0f) * invW - 1.0f;
    float ysv = (2.0f * (float)h + 1.0f) * invH - 1.0f;

    float gx =  c * xsv + s * ysv + tfx;
    float gy = -s * xsv + c * ysv + tfy;

    float ixv = ((gx + 1.0f) * (float)Ww - 1.0f) * 0.5f;
    float iyv = ((gy + 1.0f) * (float)Hh - 1.0f) * 0.5f;

    float ix0f = floorf(ixv);
    float iy0f = floorf(iyv);
    float wx1 = ixv - ix0f, wx0 = 1.0f - wx1;
    float wy1 = iyv - iy0f, wy0 = 1.0f - wy1;
    float ix1f = ix0f + 1.0f;
    float iy1f = iy0f + 1.0f;

    float mx0 = (ix0f >= 0.0f && ix0f <= (float)(Ww - 1)) ? 1.0f : 0.0f;
    float mx1 = (ix1f >= 0.0f && ix1f <= (float)(Ww - 1)) ? 1.0f : 0.0f;
    float my0 = (iy0f >= 0.0f && iy0f <= (float)(Hh - 1)) ? 1.0f : 0.0f;
    float my1 = (iy1f >= 0.0f && iy1f <= (float)(Hh - 1)) ? 1.0f : 0.0f;

    int x0 = (int)fminf(fmaxf(ix0f, 0.0f), (float)(Ww - 1));
    int x1 = (int)fminf(fmaxf(ix1f, 0.0f), (float)(Ww - 1));
    int y0 = (int)fminf(fmaxf(iy0f, 0.0f), (float)(Hh - 1));
    int y1 = (int)fminf(fmaxf(iy1f, 0.0f), (float)(Hh - 1));

    float w00 = wy0 * wx0 * (my0 * mx0);
    float w01 = wy0 * wx1 * (my0 * mx1);
    float w10 = wy1 * wx0 * (my1 * mx0);
    float w11 = wy1 * wx1 * (my1 * mx1);

    int baseB = b * (Hh * Ww);
    int o00 = (baseB + y0 * Ww + x0) * PIX_F4 + c4;
    int o01 = (baseB + y0 * Ww + x1) * PIX_F4 + c4;
    int o10 = (baseB + y1 * Ww + x0) * PIX_F4 + c4;
    int o11 = (baseB + y1 * Ww + x1) * PIX_F4 + c4;

    int outbase = pix * PIX_F4 + c4;
    int tc4 = (Tt - 1) * C4;

    // ---- Wave A: t0,t1 corners (8 loads) ----
    float4 a00 = __ldg(&in[o00 +  0]);
    float4 a01 = __ldg(&in[o01 +  0]);
    float4 a10 = __ldg(&in[o10 +  0]);
    float4 a11 = __ldg(&in[o11 +  0]);
    float4 b00 = __ldg(&in[o00 + 16]);
    float4 b01 = __ldg(&in[o01 + 16]);
    float4 b10 = __ldg(&in[o10 + 16]);
    float4 b11 = __ldg(&in[o11 + 16]);

    // ---- Wave B: t2,t3 corners (8 loads) + passthrough, issued before consuming A ----
    float4 e00 = __ldg(&in[o00 + 32]);
    float4 e01 = __ldg(&in[o01 + 32]);
    float4 e10 = __ldg(&in[o10 + 32]);
    float4 e11 = __ldg(&in[o11 + 32]);
    float4 f00 = __ldg(&in[o00 + 48]);
    float4 f01 = __ldg(&in[o01 + 48]);
    float4 f10 = __ldg(&in[o10 + 48]);
    float4 f11 = __ldg(&in[o11 + 48]);
    float4 cur = __ldcs(&in[outbase + tc4]);

    // ---- Blend + store wave A ----
    float4 r0, r1;
    r0.x = w00*a00.x + w01*a01.x + w10*a10.x + w11*a11.x;
    r0.y = w00*a00.y + w01*a01.y + w10*a10.y + w11*a11.y;
    r0.z = w00*a00.z + w01*a01.z + w10*a10.z + w11*a11.z;
    r0.w = w00*a00.w + w01*a01.w + w10*a10.w + w11*a11.w;
    r1.x = w00*b00.x + w01*b01.x + w10*b10.x + w11*b11.x;
    r1.y = w00*b00.y + w01*b01.y + w10*b10.y + w11*b11.y;
    r1.z = w00*b00.z + w01*b01.z + w10*b10.z + w11*b11.z;
    r1.w = w00*b00.w + w01*b01.w + w10*b10.w + w11*b11.w;
    __stcs(&out[outbase +  0], r0);
    __stcs(&out[outbase + 16], r1);

    // ---- Blend + store wave B ----
    float4 r2, r3;
    r2.x = w00*e00.x + w01*e01.x + w10*e10.x + w11*e11.x;
    r2.y = w00*e00.y + w01*e01.y + w10*e10.y + w11*e11.y;
    r2.z = w00*e00.z + w01*e01.z + w10*e10.z + w11*e11.z;
    r2.w = w00*e00.w + w01*e01.w + w10*e10.w + w11*e11.w;
    r3.x = w00*f00.x + w01*f01.x + w10*f10.x + w11*f11.x;
    r3.y = w00*f00.y + w01*f01.y + w10*f10.y + w11*f11.y;
    r3.z = w00*f00.z + w01*f01.z + w10*f10.z + w11*f11.z;
    r3.w = w00*f00.w + w01*f01.w + w10*f10.w + w11*f11.w;
    __stcs(&out[outbase + 32], r2);
    __stcs(&out[outbase + 48], r3);

    // ---- passthrough ----
    __stcs(&out[outbase + tc4], cur);
}

extern "C" void kernel_launch(void* const* d_in, const int* in_sizes, int n_in,
                              void* d_out, int out_size)
{
    const float4* in  = (const float4*)d_in[0];   // raw_bev_cache (4,200,200,5,64) f32
    const float*  ego = (const float*)d_in[1];    // delta_ego_motion (4,3) f32
    float4* out = (float4*)d_out;

    align_bev_mlp<<<TOTAL_BLOCKS, 256>>>(in, ego, out);
}